// round 15
// baseline (speedup 1.0000x reference)
#include <cuda_runtime.h>
#include <cuda_fp16.h>
#include <cstdint>
#include <math.h>

#define D_MODEL 1024
#define NH 16
#define HD 64
#define BATCH 4
#define SEQ 2048
#define MTOT (BATCH*SEQ)

// fp16 hi/lo scratch (rn split: hi = rn16(x), lo = rn16(x - hi))
__device__ __align__(16) __half g_xh[MTOT*D_MODEL];
__device__ __align__(16) __half g_xl[MTOT*D_MODEL];
__device__ __align__(16) __half g_ah[MTOT*D_MODEL];   // attention out (single fp16)
__device__ __align__(16) __half g_wh[4*D_MODEL*D_MODEL];
__device__ __align__(16) __half g_wl[4*D_MODEL*D_MODEL];
// Q,K split hi/lo (Q pre-scaled by log2e/8); V single fp16, transposed [b,h,d,s]
__device__ __align__(16) __half g_qh[MTOT*D_MODEL];
__device__ __align__(16) __half g_ql[MTOT*D_MODEL];
__device__ __align__(16) __half g_kh[MTOT*D_MODEL];
__device__ __align__(16) __half g_kl[MTOT*D_MODEL];
__device__ __align__(16) __half g_vth[MTOT*D_MODEL];

// ---------------- helpers ----------------
__device__ __forceinline__ uint32_t smem_u32(const void* p) {
    uint32_t a;
    asm("{ .reg .u64 t; cvta.to.shared.u64 t, %1; cvt.u32.u64 %0, t; }"
        : "=r"(a) : "l"(p));
    return a;
}
__device__ __forceinline__ void cp16(uint32_t s, const void* g) {
    asm volatile("cp.async.ca.shared.global [%0], [%1], 16;" :: "r"(s), "l"(g));
}
__device__ __forceinline__ void ldsm_x4(uint32_t r[4], uint32_t a) {
    asm volatile("ldmatrix.sync.aligned.m8n8.x4.shared.b16 {%0,%1,%2,%3}, [%4];"
        : "=r"(r[0]), "=r"(r[1]), "=r"(r[2]), "=r"(r[3]) : "r"(a));
}
__device__ __forceinline__ void mma16816(float d[4], const uint32_t a[4],
                                         uint32_t b0, uint32_t b1) {
    asm volatile("mma.sync.aligned.m16n8k16.row.col.f32.f16.f16.f32 "
        "{%0,%1,%2,%3}, {%4,%5,%6,%7}, {%8,%9}, {%0,%1,%2,%3};"
        : "+f"(d[0]), "+f"(d[1]), "+f"(d[2]), "+f"(d[3])
        : "r"(a[0]), "r"(a[1]), "r"(a[2]), "r"(a[3]), "r"(b0), "r"(b1));
}
__device__ __forceinline__ float ex2(float x) {
    float y;
    asm("ex2.approx.f32 %0, %1;" : "=f"(y) : "f"(x));
    return y;
}
__device__ __forceinline__ uint32_t f16x2(float x0, float x1) {
    __half2 h = __floats2half2_rn(x0, x1);
    return *reinterpret_cast<uint32_t*>(&h);
}
__device__ __forceinline__ uint32_t f16x2_lo(float x0, float x1, uint32_t hi) {
    __half2 h = *reinterpret_cast<__half2*>(&hi);
    float2 f = __half22float2(h);
    return f16x2(x0 - f.x, x1 - f.y);
}

// ---------------- merged fp16 hi/lo split (x + 4 weights) ----------------
__global__ __launch_bounds__(256) void allsplit_kernel(
    const float* __restrict__ x,
    const float* __restrict__ w0, const float* __restrict__ w1,
    const float* __restrict__ w2, const float* __restrict__ w3)
{
    const int NW = D_MODEL * D_MODEL;
    int i = (blockIdx.x * 256 + threadIdx.x) * 4;
    const float* src;
    __half *h, *l;
    if (blockIdx.y == 0) { src = x; h = g_xh; l = g_xl; }
    else {
        if (i >= NW) return;
        int wi = blockIdx.y - 1;
        src = (wi == 0) ? w0 : (wi == 1) ? w1 : (wi == 2) ? w2 : w3;
        h = g_wh + (size_t)wi * NW; l = g_wl + (size_t)wi * NW;
    }
    float4 v = *(const float4*)(src + i);
    uint32_t h0 = f16x2(v.x, v.y), h1 = f16x2(v.z, v.w);
    *(uint32_t*)(h + i)     = h0;
    *(uint32_t*)(h + i + 2) = h1;
    *(uint32_t*)(l + i)     = f16x2_lo(v.x, v.y, h0);
    *(uint32_t*)(l + i + 2) = f16x2_lo(v.z, v.w, h1);
}

// ---------------- HMMA fp16 GEMM: C = A[M,K] @ W[N,K]^T, BK=64 ----------
// Stage = 4 tiles of 128 rows x 64 cols (Ah,Al,Wh,Wl), 144B row stride.
// Q,K projections: 3 products. V-proj / O-proj: 1 product (slots 1,3 unused).
#define T64STR 144
#define TILE64 (128*T64STR)       // 18432
#define STAGE64 (4*TILE64)        // 73728
#define GEMM_SMEM (2*STAGE64)     // 147456

__device__ __forceinline__ void load_stage(uint32_t sb, int stage, int k0,
    const __half* Ah, const __half* Al,
    const __half* Wh, const __half* Wl, int m0, int n0, bool full3)
{
    uint32_t st = sb + stage * STAGE64;
#pragma unroll
    for (int t = 0; t < 4; t++) {
        int chunk = threadIdx.x + t * 256;        // 0..1023
        int row = chunk >> 3, c = chunk & 7;      // 128 rows x 8 chunks of 8 fp16
        uint32_t so = row * T64STR + c * 16;
        size_t ga = (size_t)(m0 + row) * D_MODEL + k0 + c * 8;
        size_t gb = (size_t)(n0 + row) * D_MODEL + k0 + c * 8;
        cp16(st + 0*TILE64 + so, Ah + ga);
        cp16(st + 2*TILE64 + so, Wh + gb);
        if (full3) {
            cp16(st + 1*TILE64 + so, Al + ga);
            cp16(st + 3*TILE64 + so, Wl + gb);
        }
    }
    asm volatile("cp.async.commit_group;" ::: "memory");
}

__global__ __launch_bounds__(256, 1) void mma_gemm_kernel(float* __restrict__ out_o, int mode)
{
    extern __shared__ char smem[];
    uint32_t sb = smem_u32(smem);
    int tid = threadIdx.x, wid = tid >> 5, lane = tid & 31;

    int m0 = blockIdx.x * 128;
    int nb = blockIdx.y;
    int widx, n0;
    const __half *Ah, *Al;
    if (mode == 0) { widx = nb >> 3; n0 = (nb & 7) * 128; Ah = g_xh; Al = g_xl; }
    else           { widx = 3;       n0 = nb * 128;       Ah = g_ah; Al = g_ah; }
    const __half* Wh = g_wh + (size_t)widx * D_MODEL * D_MODEL;
    const __half* Wl = g_wl + (size_t)widx * D_MODEL * D_MODEL;

    const bool full3 = (mode == 0) && (widx < 2);

    int wm = (wid & 1) * 64;
    int wn = (wid >> 1) * 32;

    float acc[4][4][4];
#pragma unroll
    for (int i = 0; i < 4; i++)
#pragma unroll
        for (int j = 0; j < 4; j++)
#pragma unroll
            for (int r = 0; r < 4; r++) acc[i][j][r] = 0.f;

    int lr = lane & 15;
    int lc = (lane >> 4) * 8;

    load_stage(sb, 0, 0, Ah, Al, Wh, Wl, m0, n0, full3);

    for (int it = 0; it < 16; it++) {
        int stage = it & 1;
        asm volatile("cp.async.wait_group 0;" ::: "memory");
        __syncthreads();   // stage data visible to all; prev reads done
        if (it + 1 < 16)
            load_stage(sb, stage ^ 1, (it + 1) * 64, Ah, Al, Wh, Wl, m0, n0, full3);

        uint32_t st = sb + stage * STAGE64;
        uint32_t aH = st + 0*TILE64, aL = st + 1*TILE64;
        uint32_t bH = st + 2*TILE64, bL = st + 3*TILE64;

#pragma unroll
        for (int ks = 0; ks < 4; ks++) {
            int kb = ks * 16;
            uint32_t ahf[4][4], bhf[2][4];
#pragma unroll
            for (int mi = 0; mi < 4; mi++) {
                uint32_t ro = (uint32_t)(wm + mi*16 + lr) * T64STR + (kb + lc) * 2;
                ldsm_x4(ahf[mi], aH + ro);
            }
#pragma unroll
            for (int p = 0; p < 2; p++) {
                uint32_t ro = (uint32_t)(wn + p*16 + lr) * T64STR + (kb + lc) * 2;
                ldsm_x4(bhf[p], bH + ro);
            }
#pragma unroll
            for (int mi = 0; mi < 4; mi++)
#pragma unroll
                for (int ni = 0; ni < 4; ni++)
                    mma16816(acc[mi][ni], ahf[mi], bhf[ni>>1][ni&1], bhf[ni>>1][(ni&1)+2]);
            if (full3) {
                uint32_t alf[4][4], blf[2][4];
#pragma unroll
                for (int mi = 0; mi < 4; mi++) {
                    uint32_t ro = (uint32_t)(wm + mi*16 + lr) * T64STR + (kb + lc) * 2;
                    ldsm_x4(alf[mi], aL + ro);
                }
#pragma unroll
                for (int p = 0; p < 2; p++) {
                    uint32_t ro = (uint32_t)(wn + p*16 + lr) * T64STR + (kb + lc) * 2;
                    ldsm_x4(blf[p], bL + ro);
                }
#pragma unroll
                for (int mi = 0; mi < 4; mi++)
#pragma unroll
                    for (int ni = 0; ni < 4; ni++)
                        mma16816(acc[mi][ni], alf[mi], bhf[ni>>1][ni&1], bhf[ni>>1][(ni&1)+2]);
#pragma unroll
                for (int mi = 0; mi < 4; mi++)
#pragma unroll
                    for (int ni = 0; ni < 4; ni++)
                        mma16816(acc[mi][ni], ahf[mi], blf[ni>>1][ni&1], blf[ni>>1][(ni&1)+2]);
            }
        }
    }

    // Epilogue
    int qr = lane >> 2, qc = (lane & 3) * 2;
    float scl = (mode == 0 && widx == 0) ? 0.125f * 1.4426950408889634f : 1.f;
#pragma unroll
    for (int mi = 0; mi < 4; mi++) {
#pragma unroll
        for (int ni = 0; ni < 4; ni++) {
            int r0 = m0 + wm + mi*16 + qr;
            int cN = n0 + wn + ni*8 + qc;
            float v0 = acc[mi][ni][0]*scl, v1 = acc[mi][ni][1]*scl;
            float v2 = acc[mi][ni][2]*scl, v3 = acc[mi][ni][3]*scl;
            if (mode == 0) {
                int h = cN >> 6, d = cN & 63;
                int b0 = r0 / SEQ, ss = r0 % SEQ;
                if (widx == 0) {         // Q: hi/lo
                    size_t a0 = (((size_t)(b0*NH + h))*SEQ + ss)*HD + d;
                    size_t a1 = a0 + 8*HD;
                    uint32_t h0 = f16x2(v0, v1), h1 = f16x2(v2, v3);
                    *(uint32_t*)(g_qh + a0) = h0;
                    *(uint32_t*)(g_ql + a0) = f16x2_lo(v0, v1, h0);
                    *(uint32_t*)(g_qh + a1) = h1;
                    *(uint32_t*)(g_ql + a1) = f16x2_lo(v2, v3, h1);
                } else if (widx == 1) {  // K: hi/lo
                    size_t a0 = (((size_t)(b0*NH + h))*SEQ + ss)*HD + d;
                    size_t a1 = a0 + 8*HD;
                    uint32_t h0 = f16x2(v0, v1), h1 = f16x2(v2, v3);
                    *(uint32_t*)(g_kh + a0) = h0;
                    *(uint32_t*)(g_kl + a0) = f16x2_lo(v0, v1, h0);
                    *(uint32_t*)(g_kh + a1) = h1;
                    *(uint32_t*)(g_kl + a1) = f16x2_lo(v2, v3, h1);
                } else {                 // V transposed [b,h,d,s]: single fp16
                    size_t base = ((size_t)(b0*NH + h)) * HD;
                    g_vth[(base + d  )*SEQ + ss]     = __float2half_rn(v0);
                    g_vth[(base + d+1)*SEQ + ss]     = __float2half_rn(v1);
                    g_vth[(base + d  )*SEQ + ss + 8] = __float2half_rn(v2);
                    g_vth[(base + d+1)*SEQ + ss + 8] = __float2half_rn(v3);
                }
            } else {
                float2* p0 = (float2*)(out_o + (size_t)r0 * D_MODEL + cN);
                float2* p1 = (float2*)(out_o + (size_t)(r0+8) * D_MODEL + cN);
                *p0 = make_float2(v0, v1);
                *p1 = make_float2(v2, v3);
            }
        }
    }
}

// ---------------- HMMA fp16 causal flash attention, KV tiles of 128 -------
// Buffer: Kh (128x144B) | Kl (128x144B) | Vth (64x272B) = 54272; two buffers.
#define QSTR 144
#define KSTR 144
#define VSTR 272
#define A_KL 18432
#define A_VH 36864
#define BUF_SZ 54272
#define ATTN_SMEM (2*BUF_SZ)   // 108544 -> 1 CTA/SM

__device__ __forceinline__ void attn_load_kv(uint32_t sb, int buf, int t, int tid,
    const __half* Kh, const __half* Kl, const __half* Vth)
{
    uint32_t kb = sb + buf * BUF_SZ;
#pragma unroll
    for (int p = 0; p < 4; p++) {
        int i = tid + p*256;          // 0..1023: 128 rows x 8 chunks
        int row = i >> 3, c = i & 7;
        size_t g = (size_t)(t*128 + row)*HD + c*8;
        cp16(kb + row*KSTR + c*16, Kh + g);
        cp16(kb + A_KL + row*KSTR + c*16, Kl + g);
    }
#pragma unroll
    for (int p = 0; p < 4; p++) {
        int i = tid + p*256;          // 0..1023: 64 d-rows x 16 chunks
        int d = i >> 4, c = i & 15;
        size_t g = (size_t)d*SEQ + t*128 + c*8;
        cp16(kb + A_VH + d*VSTR + c*16, Vth + g);
    }
    asm volatile("cp.async.commit_group;" ::: "memory");
}

__global__ __launch_bounds__(256, 1) void attn_mma_kernel()
{
    extern __shared__ char smem[];
    uint32_t sb = smem_u32(smem);
    int tid = threadIdx.x, wid = tid >> 5, lane = tid & 31;
    int qb = gridDim.x - 1 - blockIdx.x;        // long CTAs first
    int q0 = qb * 128, bh = blockIdx.y;
    int nt = qb + 1;                             // KV-128 tiles

    const __half* Qh  = g_qh  + (size_t)bh * SEQ * HD;
    const __half* Ql  = g_ql  + (size_t)bh * SEQ * HD;
    const __half* Kh  = g_kh  + (size_t)bh * SEQ * HD;
    const __half* Kl  = g_kl  + (size_t)bh * SEQ * HD;
    const __half* Vth = g_vth + (size_t)bh * HD * SEQ;

    // Stage Q through buffer 0 (hi at 0, lo at +18432); freed before kv0 lands
#pragma unroll
    for (int p = 0; p < 4; p++) {
        int i = tid + p*256;
        int row = i >> 3, c = i & 7;
        size_t g = (size_t)(q0 + row)*HD + c*8;
        cp16(sb + row*QSTR + c*16, Qh + g);
        cp16(sb + A_KL + row*QSTR + c*16, Ql + g);
    }
    asm volatile("cp.async.commit_group;" ::: "memory");
    asm volatile("cp.async.wait_group 0;" ::: "memory");
    __syncthreads();   // Q visible to all

    int lr = lane & 15, lc = (lane >> 4) * 8;
    uint32_t aqh[4][4], aql[4][4];
#pragma unroll
    for (int kd = 0; kd < 4; kd++) {
        uint32_t ro = (uint32_t)(wid*16 + lr) * QSTR + (kd*16 + lc) * 2;
        ldsm_x4(aqh[kd], sb + ro);
        ldsm_x4(aql[kd], sb + A_KL + ro);
    }
    __syncthreads();   // Q reads done: buffers free for KV

    attn_load_kv(sb, 0, 0, tid, Kh, Kl, Vth);
    if (nt > 1) {
        attn_load_kv(sb, 1, 1, tid, Kh, Kl, Vth);
        asm volatile("cp.async.wait_group 1;" ::: "memory");   // kv0 done
    } else {
        asm volatile("cp.async.wait_group 0;" ::: "memory");   // kv0 done (only group)
    }
    __syncthreads();   // kv0 visible to ALL threads

    float o[8][4];
#pragma unroll
    for (int j = 0; j < 8; j++)
#pragma unroll
        for (int e = 0; e < 4; e++) o[j][e] = 0.f;
    float m0r = -1e30f, m1r = -1e30f, l0 = 0.f, l1 = 0.f;

    int r0g = q0 + wid*16 + (lane >> 2);
    int cl2 = 2*(lane & 3);

    for (int t = 0; t < nt; t++) {
        int buf = t & 1;
        uint32_t kb = sb + buf * BUF_SZ;

        // S = Q K^T (fp16x3), 128 cols
        float s[16][4];
#pragma unroll
        for (int j = 0; j < 16; j++)
#pragma unroll
            for (int e = 0; e < 4; e++) s[j][e] = 0.f;
#pragma unroll
        for (int p = 0; p < 8; p++) {
#pragma unroll
            for (int kd = 0; kd < 4; kd++) {
                uint32_t bh4[4], bl4[4];
                uint32_t ro = (uint32_t)(p*16 + lr) * KSTR + (kd*16 + lc) * 2;
                ldsm_x4(bh4, kb + ro);
                ldsm_x4(bl4, kb + A_KL + ro);
                mma16816(s[2*p],   aqh[kd], bh4[0], bh4[2]);
                mma16816(s[2*p+1], aqh[kd], bh4[1], bh4[3]);
                mma16816(s[2*p],   aql[kd], bh4[0], bh4[2]);
                mma16816(s[2*p+1], aql[kd], bh4[1], bh4[3]);
                mma16816(s[2*p],   aqh[kd], bl4[0], bl4[2]);
                mma16816(s[2*p+1], aqh[kd], bl4[1], bl4[3]);
            }
        }

        // causal mask (only the diagonal tile crosses)
        if (t == qb) {
            int r1g = r0g + 8;
#pragma unroll
            for (int j = 0; j < 16; j++) {
                int c0 = 128*t + 8*j + cl2;
                if (c0     > r0g) s[j][0] = -1e30f;
                if (c0 + 1 > r0g) s[j][1] = -1e30f;
                if (c0     > r1g) s[j][2] = -1e30f;
                if (c0 + 1 > r1g) s[j][3] = -1e30f;
            }
        }

        // online softmax (log2 domain; Q pre-scaled by log2e/8)
        float rm0 = -1e30f, rm1 = -1e30f;
#pragma unroll
        for (int j = 0; j < 16; j++) {
            rm0 = fmaxf(rm0, fmaxf(s[j][0], s[j][1]));
            rm1 = fmaxf(rm1, fmaxf(s[j][2], s[j][3]));
        }
        rm0 = fmaxf(rm0, __shfl_xor_sync(0xffffffffu, rm0, 1));
        rm0 = fmaxf(rm0, __shfl_xor_sync(0xffffffffu, rm0, 2));
        rm1 = fmaxf(rm1, __shfl_xor_sync(0xffffffffu, rm1, 1));
        rm1 = fmaxf(rm1, __shfl_xor_sync(0xffffffffu, rm1, 2));
        float mn0 = fmaxf(m0r, rm0), mn1 = fmaxf(m1r, rm1);
        float a0 = ex2(m0r - mn0), a1 = ex2(m1r - mn1);
        float sum0 = 0.f, sum1 = 0.f;
#pragma unroll
        for (int j = 0; j < 16; j++) {
            s[j][0] = ex2(s[j][0] - mn0);
            s[j][1] = ex2(s[j][1] - mn0);
            s[j][2] = ex2(s[j][2] - mn1);
            s[j][3] = ex2(s[j][3] - mn1);
            sum0 += s[j][0] + s[j][1];
            sum1 += s[j][2] + s[j][3];
        }
        sum0 += __shfl_xor_sync(0xffffffffu, sum0, 1);
        sum0 += __shfl_xor_sync(0xffffffffu, sum0, 2);
        sum1 += __shfl_xor_sync(0xffffffffu, sum1, 1);
        sum1 += __shfl_xor_sync(0xffffffffu, sum1, 2);
        l0 = l0 * a0 + sum0;  l1 = l1 * a1 + sum1;
        m0r = mn0;  m1r = mn1;
#pragma unroll
        for (int j = 0; j < 8; j++) {
            o[j][0] *= a0; o[j][1] *= a0; o[j][2] *= a1; o[j][3] *= a1;
        }

        // O += P @ V (single product: P rn fp16, V single)
#pragma unroll
        for (int kk = 0; kk < 8; kk++) {
            uint32_t ph[4];
            ph[0] = f16x2(s[2*kk][0],   s[2*kk][1]);
            ph[1] = f16x2(s[2*kk][2],   s[2*kk][3]);
            ph[2] = f16x2(s[2*kk+1][0], s[2*kk+1][1]);
            ph[3] = f16x2(s[2*kk+1][2], s[2*kk+1][3]);
#pragma unroll
            for (int pd = 0; pd < 4; pd++) {
                uint32_t vh4[4];
                uint32_t ro = (uint32_t)(pd*16 + lr) * VSTR + (kk*16 + lc) * 2;
                ldsm_x4(vh4, kb + A_VH + ro);
                mma16816(o[2*pd],   ph, vh4[0], vh4[2]);
                mma16816(o[2*pd+1], ph, vh4[1], vh4[3]);
            }
        }

        // pipeline: ensure t+1 visible, recycle buf for t+2
        if (t + 1 < nt) {
            asm volatile("cp.async.wait_group 0;" ::: "memory");
            __syncthreads();   // all done reading buf; t+1 visible to all
            if (t + 2 < nt)
                attn_load_kv(sb, buf, t + 2, tid, Kh, Kl, Vth);
        }
    }

    // epilogue: normalize, single rn fp16, write [B,S,D]
    float i0 = 1.f / l0, i1 = 1.f / l1;
    int b = bh >> 4, h = bh & 15;
    int s0 = q0 + wid*16 + (lane >> 2);
#pragma unroll
    for (int j = 0; j < 8; j++) {
        int d = h*64 + 8*j + cl2;
        size_t a0 = ((size_t)b*SEQ + s0) * D_MODEL + d;
        size_t a1 = a0 + (size_t)8 * D_MODEL;
        *(uint32_t*)(g_ah + a0) = f16x2(o[j][0]*i0, o[j][1]*i0);
        *(uint32_t*)(g_ah + a1) = f16x2(o[j][2]*i1, o[j][3]*i1);
    }
}

extern "C" void kernel_launch(void* const* d_in, const int* in_sizes, int n_in,
                              void* d_out, int out_size)
{
    const float* x  = (const float*)d_in[0];
    const float* wq = (const float*)d_in[1];
    const float* wk = (const float*)d_in[2];
    const float* wv = (const float*)d_in[3];
    const float* wo = (const float*)d_in[4];
    float* out = (float*)d_out;

    cudaFuncSetAttribute(mma_gemm_kernel,
                         cudaFuncAttributeMaxDynamicSharedMemorySize, GEMM_SMEM);
    cudaFuncSetAttribute(attn_mma_kernel,
                         cudaFuncAttributeMaxDynamicSharedMemorySize, ATTN_SMEM);

    const int NX = MTOT * D_MODEL;

    dim3 gs(NX/4/256, 5);
    allsplit_kernel<<<gs, 256>>>(x, wq, wk, wv, wo);

    // QKV projection (Q,K hi/lo 3-prod; V 1-prod -> fp16 V^T), all BK64
    dim3 g1(MTOT/128, 24);
    mma_gemm_kernel<<<g1, 256, GEMM_SMEM>>>(nullptr, 0);

    // tensor-core causal flash attention (KV-128 tiles, single-fp16 output)
    dim3 g2(SEQ/128, BATCH*NH);
    attn_mma_kernel<<<g2, 256, ATTN_SMEM>>>();

    // O-projection (1-prod BK64)
    dim3 g3(MTOT/128, D_MODEL/128);
    mma_gemm_kernel<<<g3, 256, GEMM_SMEM>>>(out, 1);
}

// round 16
// speedup vs baseline: 1.0199x; 1.0199x over previous
#include <cuda_runtime.h>
#include <cuda_fp16.h>
#include <cstdint>
#include <math.h>

#define D_MODEL 1024
#define NH 16
#define HD 64
#define BATCH 4
#define SEQ 2048
#define MTOT (BATCH*SEQ)

// fp16 hi/lo scratch (rn split: hi = rn16(x), lo = rn16(x - hi))
__device__ __align__(16) __half g_xh[MTOT*D_MODEL];
__device__ __align__(16) __half g_xl[MTOT*D_MODEL];
__device__ __align__(16) __half g_ah[MTOT*D_MODEL];   // attention out (single fp16)
__device__ __align__(16) __half g_wh[4*D_MODEL*D_MODEL];
__device__ __align__(16) __half g_wl[4*D_MODEL*D_MODEL];
// Q,K split hi/lo (Q pre-scaled by log2e/8); V single fp16, transposed [b,h,d,s]
__device__ __align__(16) __half g_qh[MTOT*D_MODEL];
__device__ __align__(16) __half g_ql[MTOT*D_MODEL];
__device__ __align__(16) __half g_kh[MTOT*D_MODEL];
__device__ __align__(16) __half g_kl[MTOT*D_MODEL];
__device__ __align__(16) __half g_vth[MTOT*D_MODEL];

// ---------------- helpers ----------------
__device__ __forceinline__ uint32_t smem_u32(const void* p) {
    uint32_t a;
    asm("{ .reg .u64 t; cvta.to.shared.u64 t, %1; cvt.u32.u64 %0, t; }"
        : "=r"(a) : "l"(p));
    return a;
}
__device__ __forceinline__ void cp16(uint32_t s, const void* g) {
    asm volatile("cp.async.ca.shared.global [%0], [%1], 16;" :: "r"(s), "l"(g));
}
__device__ __forceinline__ void ldsm_x4(uint32_t r[4], uint32_t a) {
    asm volatile("ldmatrix.sync.aligned.m8n8.x4.shared.b16 {%0,%1,%2,%3}, [%4];"
        : "=r"(r[0]), "=r"(r[1]), "=r"(r[2]), "=r"(r[3]) : "r"(a));
}
__device__ __forceinline__ void mma16816(float d[4], const uint32_t a[4],
                                         uint32_t b0, uint32_t b1) {
    asm volatile("mma.sync.aligned.m16n8k16.row.col.f32.f16.f16.f32 "
        "{%0,%1,%2,%3}, {%4,%5,%6,%7}, {%8,%9}, {%0,%1,%2,%3};"
        : "+f"(d[0]), "+f"(d[1]), "+f"(d[2]), "+f"(d[3])
        : "r"(a[0]), "r"(a[1]), "r"(a[2]), "r"(a[3]), "r"(b0), "r"(b1));
}
__device__ __forceinline__ float ex2(float x) {
    float y;
    asm("ex2.approx.f32 %0, %1;" : "=f"(y) : "f"(x));
    return y;
}
__device__ __forceinline__ uint32_t f16x2(float x0, float x1) {
    __half2 h = __floats2half2_rn(x0, x1);
    return *reinterpret_cast<uint32_t*>(&h);
}
__device__ __forceinline__ uint32_t f16x2_lo(float x0, float x1, uint32_t hi) {
    __half2 h = *reinterpret_cast<__half2*>(&hi);
    float2 f = __half22float2(h);
    return f16x2(x0 - f.x, x1 - f.y);
}

// ---------------- merged fp16 hi/lo split (x + 4 weights), 8 floats/thread --
// lo is skipped for wv/wo (their GEMMs are 1-product and never read Wl).
__global__ __launch_bounds__(256) void allsplit_kernel(
    const float* __restrict__ x,
    const float* __restrict__ w0, const float* __restrict__ w1,
    const float* __restrict__ w2, const float* __restrict__ w3)
{
    const int NW = D_MODEL * D_MODEL;
    int i = (blockIdx.x * 256 + threadIdx.x) * 8;
    const float* src;
    __half *h, *l;
    bool need_lo = true;
    if (blockIdx.y == 0) { src = x; h = g_xh; l = g_xl; }
    else {
        if (i >= NW) return;
        int wi = blockIdx.y - 1;
        src = (wi == 0) ? w0 : (wi == 1) ? w1 : (wi == 2) ? w2 : w3;
        h = g_wh + (size_t)wi * NW; l = g_wl + (size_t)wi * NW;
        need_lo = (wi < 2);   // only wq, wk GEMMs read Wl
    }
#pragma unroll
    for (int q = 0; q < 2; q++) {
        float4 v = *(const float4*)(src + i + q*4);
        uint32_t h0 = f16x2(v.x, v.y), h1 = f16x2(v.z, v.w);
        *(uint32_t*)(h + i + q*4)     = h0;
        *(uint32_t*)(h + i + q*4 + 2) = h1;
        if (need_lo) {
            *(uint32_t*)(l + i + q*4)     = f16x2_lo(v.x, v.y, h0);
            *(uint32_t*)(l + i + q*4 + 2) = f16x2_lo(v.z, v.w, h1);
        }
    }
}

// ---------------- HMMA fp16 GEMM: C = A[M,K] @ W[N,K]^T ----------------
// Q,K projections: 3 products, BK=32 (slots: Ah,Al,Wh,Wl).
// V-proj / O-proj: 1 product, BK=64 (slots hold TWO k-chunks of Ah,Wh).
#define TSTRIDE 80
#define TILE_B  (128*TSTRIDE)
#define STAGE_B (4*TILE_B)
#define GEMM_SMEM (2*STAGE_B)

__device__ __forceinline__ void load_stage(uint32_t sb, int stage, int k0,
    const __half* Ah, const __half* Al,
    const __half* Wh, const __half* Wl, int m0, int n0, bool full3)
{
    uint32_t st = sb + stage * STAGE_B;
#pragma unroll
    for (int t = 0; t < 2; t++) {
        int chunk = threadIdx.x + t * 256;
        int row = chunk >> 2, cc = chunk & 3;
        uint32_t so = row * TSTRIDE + cc * 16;
        size_t ga = (size_t)(m0 + row) * D_MODEL + k0 + cc * 8;
        size_t gb = (size_t)(n0 + row) * D_MODEL + k0 + cc * 8;
        cp16(st + 0*TILE_B + so, Ah + ga);
        cp16(st + 2*TILE_B + so, Wh + gb);
        if (full3) {
            cp16(st + 1*TILE_B + so, Al + ga);
            cp16(st + 3*TILE_B + so, Wl + gb);
        } else {   // second k-chunk (k0+32) into the spare slots
            cp16(st + 1*TILE_B + so, Ah + ga + 32);
            cp16(st + 3*TILE_B + so, Wh + gb + 32);
        }
    }
    asm volatile("cp.async.commit_group;" ::: "memory");
}

__global__ __launch_bounds__(256, 2) void mma_gemm_kernel(float* __restrict__ out_o, int mode)
{
    extern __shared__ char smem[];
    uint32_t sb = smem_u32(smem);
    int tid = threadIdx.x, wid = tid >> 5, lane = tid & 31;

    int m0 = blockIdx.x * 128;
    int nb = blockIdx.y;
    int widx, n0;
    const __half *Ah, *Al;
    if (mode == 0) { widx = nb >> 3; n0 = (nb & 7) * 128; Ah = g_xh; Al = g_xl; }
    else           { widx = 3;       n0 = nb * 128;       Ah = g_ah; Al = g_ah; }
    const __half* Wh = g_wh + (size_t)widx * D_MODEL * D_MODEL;
    const __half* Wl = g_wl + (size_t)widx * D_MODEL * D_MODEL;

    // 3-product only for Q,K projections (softmax-amplified); V/O: 1 product
    const bool full3 = (mode == 0) && (widx < 2);
    const int kstep = full3 ? 32 : 64;
    const int niter = D_MODEL / kstep;

    int wm = (wid & 1) * 64;
    int wn = (wid >> 1) * 32;

    float acc[4][4][4];
#pragma unroll
    for (int i = 0; i < 4; i++)
#pragma unroll
        for (int j = 0; j < 4; j++)
#pragma unroll
            for (int r = 0; r < 4; r++) acc[i][j][r] = 0.f;

    int lr = lane & 15;
    int lc = (lane >> 4) * 8;

    load_stage(sb, 0, 0, Ah, Al, Wh, Wl, m0, n0, full3);

    for (int it = 0; it < niter; it++) {
        int stage = it & 1;
        asm volatile("cp.async.wait_group 0;" ::: "memory");
        __syncthreads();   // stage data visible to all; prev reads done
        if (it + 1 < niter)
            load_stage(sb, stage ^ 1, (it + 1) * kstep, Ah, Al, Wh, Wl, m0, n0, full3);

        uint32_t st = sb + stage * STAGE_B;

        if (full3) {
            uint32_t aH = st + 0*TILE_B, aL = st + 1*TILE_B;
            uint32_t bH = st + 2*TILE_B, bL = st + 3*TILE_B;
#pragma unroll
            for (int ks = 0; ks < 2; ks++) {
                int kb = ks * 16;
                uint32_t ahf[4][4], bhf[2][4];
#pragma unroll
                for (int mi = 0; mi < 4; mi++) {
                    uint32_t ro = (uint32_t)(wm + mi*16 + lr) * TSTRIDE + (kb + lc) * 2;
                    ldsm_x4(ahf[mi], aH + ro);
                }
#pragma unroll
                for (int p = 0; p < 2; p++) {
                    uint32_t ro = (uint32_t)(wn + p*16 + lr) * TSTRIDE + (kb + lc) * 2;
                    ldsm_x4(bhf[p], bH + ro);
                }
#pragma unroll
                for (int mi = 0; mi < 4; mi++)
#pragma unroll
                    for (int ni = 0; ni < 4; ni++)
                        mma16816(acc[mi][ni], ahf[mi], bhf[ni>>1][ni&1], bhf[ni>>1][(ni&1)+2]);
                uint32_t alf[4][4], blf[2][4];
#pragma unroll
                for (int mi = 0; mi < 4; mi++) {
                    uint32_t ro = (uint32_t)(wm + mi*16 + lr) * TSTRIDE + (kb + lc) * 2;
                    ldsm_x4(alf[mi], aL + ro);
                }
#pragma unroll
                for (int p = 0; p < 2; p++) {
                    uint32_t ro = (uint32_t)(wn + p*16 + lr) * TSTRIDE + (kb + lc) * 2;
                    ldsm_x4(blf[p], bL + ro);
                }
#pragma unroll
                for (int mi = 0; mi < 4; mi++)
#pragma unroll
                    for (int ni = 0; ni < 4; ni++)
                        mma16816(acc[mi][ni], alf[mi], bhf[ni>>1][ni&1], bhf[ni>>1][(ni&1)+2]);
#pragma unroll
                for (int mi = 0; mi < 4; mi++)
#pragma unroll
                    for (int ni = 0; ni < 4; ni++)
                        mma16816(acc[mi][ni], ahf[mi], blf[ni>>1][ni&1], blf[ni>>1][(ni&1)+2]);
            }
        } else {
            // 1-product, two k-chunks per stage (4 x k16 sub-steps)
#pragma unroll
            for (int ks = 0; ks < 4; ks++) {
                uint32_t aT = st + ((ks >> 1) ? 1 : 0) * TILE_B;
                uint32_t bT = st + ((ks >> 1) ? 3 : 2) * TILE_B;
                int kb = (ks & 1) * 16;
                uint32_t ahf[4][4], bhf[2][4];
#pragma unroll
                for (int mi = 0; mi < 4; mi++) {
                    uint32_t ro = (uint32_t)(wm + mi*16 + lr) * TSTRIDE + (kb + lc) * 2;
                    ldsm_x4(ahf[mi], aT + ro);
                }
#pragma unroll
                for (int p = 0; p < 2; p++) {
                    uint32_t ro = (uint32_t)(wn + p*16 + lr) * TSTRIDE + (kb + lc) * 2;
                    ldsm_x4(bhf[p], bT + ro);
                }
#pragma unroll
                for (int mi = 0; mi < 4; mi++)
#pragma unroll
                    for (int ni = 0; ni < 4; ni++)
                        mma16816(acc[mi][ni], ahf[mi], bhf[ni>>1][ni&1], bhf[ni>>1][(ni&1)+2]);
            }
        }
    }

    // Epilogue
    int qr = lane >> 2, qc = (lane & 3) * 2;
    float scl = (mode == 0 && widx == 0) ? 0.125f * 1.4426950408889634f : 1.f;
#pragma unroll
    for (int mi = 0; mi < 4; mi++) {
#pragma unroll
        for (int ni = 0; ni < 4; ni++) {
            int r0 = m0 + wm + mi*16 + qr;
            int cN = n0 + wn + ni*8 + qc;
            float v0 = acc[mi][ni][0]*scl, v1 = acc[mi][ni][1]*scl;
            float v2 = acc[mi][ni][2]*scl, v3 = acc[mi][ni][3]*scl;
            if (mode == 0) {
                int h = cN >> 6, d = cN & 63;
                int b0 = r0 / SEQ, ss = r0 % SEQ;
                if (widx == 0) {         // Q: hi/lo
                    size_t a0 = (((size_t)(b0*NH + h))*SEQ + ss)*HD + d;
                    size_t a1 = a0 + 8*HD;
                    uint32_t h0 = f16x2(v0, v1), h1 = f16x2(v2, v3);
                    *(uint32_t*)(g_qh + a0) = h0;
                    *(uint32_t*)(g_ql + a0) = f16x2_lo(v0, v1, h0);
                    *(uint32_t*)(g_qh + a1) = h1;
                    *(uint32_t*)(g_ql + a1) = f16x2_lo(v2, v3, h1);
                } else if (widx == 1) {  // K: hi/lo
                    size_t a0 = (((size_t)(b0*NH + h))*SEQ + ss)*HD + d;
                    size_t a1 = a0 + 8*HD;
                    uint32_t h0 = f16x2(v0, v1), h1 = f16x2(v2, v3);
                    *(uint32_t*)(g_kh + a0) = h0;
                    *(uint32_t*)(g_kl + a0) = f16x2_lo(v0, v1, h0);
                    *(uint32_t*)(g_kh + a1) = h1;
                    *(uint32_t*)(g_kl + a1) = f16x2_lo(v2, v3, h1);
                } else {                 // V transposed [b,h,d,s]: single fp16
                    size_t base = ((size_t)(b0*NH + h)) * HD;
                    g_vth[(base + d  )*SEQ + ss]     = __float2half_rn(v0);
                    g_vth[(base + d+1)*SEQ + ss]     = __float2half_rn(v1);
                    g_vth[(base + d  )*SEQ + ss + 8] = __float2half_rn(v2);
                    g_vth[(base + d+1)*SEQ + ss + 8] = __float2half_rn(v3);
                }
            } else {
                float2* p0 = (float2*)(out_o + (size_t)r0 * D_MODEL + cN);
                float2* p1 = (float2*)(out_o + (size_t)(r0+8) * D_MODEL + cN);
                *p0 = make_float2(v0, v1);
                *p1 = make_float2(v2, v3);
            }
        }
    }
}

// ---------------- HMMA fp16 causal flash attention ----------------
#define QSTR 144
#define KSTR 144
#define VSTR 144
#define A_KL 9216
#define A_VH 18432
#define BUF_SZ 27648
#define ATTN_SMEM (2*BUF_SZ)   // 55296 -> 2 CTAs/SM

__device__ __forceinline__ void attn_load_kv(uint32_t sb, int buf, int t, int tid,
    const __half* Kh, const __half* Kl, const __half* Vth)
{
    uint32_t kb = sb + buf * BUF_SZ;
#pragma unroll
    for (int p = 0; p < 2; p++) {
        int i = tid + p*256;          // 0..511
        int row = i >> 3, c = i & 7;  // 64 rows x 8 chunks of 8 fp16
        size_t g = (size_t)(t*64 + row)*HD + c*8;
        cp16(kb + row*KSTR + c*16, Kh + g);
        cp16(kb + A_KL + row*KSTR + c*16, Kl + g);
    }
#pragma unroll
    for (int p = 0; p < 2; p++) {
        int i = tid + p*256;
        int d = i >> 3, c = i & 7;    // 64 d-rows x 8 chunks
        size_t g = (size_t)d*SEQ + t*64 + c*8;
        cp16(kb + A_VH + d*VSTR + c*16, Vth + g);
    }
    asm volatile("cp.async.commit_group;" ::: "memory");
}

__global__ __launch_bounds__(256, 2) void attn_mma_kernel()
{
    extern __shared__ char smem[];
    uint32_t sb = smem_u32(smem);
    int tid = threadIdx.x, wid = tid >> 5, lane = tid & 31;
    int qb = gridDim.x - 1 - blockIdx.x;        // long CTAs first
    int q0 = qb * 128, bh = blockIdx.y;
    int nt = 2*qb + 2;

    const __half* Qh  = g_qh  + (size_t)bh * SEQ * HD;
    const __half* Ql  = g_ql  + (size_t)bh * SEQ * HD;
    const __half* Kh  = g_kh  + (size_t)bh * SEQ * HD;
    const __half* Kl  = g_kl  + (size_t)bh * SEQ * HD;
    const __half* Vth = g_vth + (size_t)bh * HD * SEQ;

    // Stage Q: hi at sb, lo at sb+18432 (spans both KV buffers; freed before use)
#pragma unroll
    for (int p = 0; p < 4; p++) {
        int i = tid + p*256;          // 0..1023: 128 rows x 8 chunks
        int row = i >> 3, c = i & 7;
        size_t g = (size_t)(q0 + row)*HD + c*8;
        cp16(sb + row*QSTR + c*16, Qh + g);
        cp16(sb + 18432 + row*QSTR + c*16, Ql + g);
    }
    asm volatile("cp.async.commit_group;" ::: "memory");
    asm volatile("cp.async.wait_group 0;" ::: "memory");
    __syncthreads();   // Q visible to all

    int lr = lane & 15, lc = (lane >> 4) * 8;
    uint32_t aqh[4][4], aql[4][4];
#pragma unroll
    for (int kd = 0; kd < 4; kd++) {
        uint32_t ro = (uint32_t)(wid*16 + lr) * QSTR + (kd*16 + lc) * 2;
        ldsm_x4(aqh[kd], sb + ro);
        ldsm_x4(aql[kd], sb + 18432 + ro);
    }
    __syncthreads();   // Q reads done: buffers free for KV

    attn_load_kv(sb, 0, 0, tid, Kh, Kl, Vth);
    if (nt > 1) attn_load_kv(sb, 1, 1, tid, Kh, Kl, Vth);
    asm volatile("cp.async.wait_group %0;" :: "n"(1) : "memory");
    __syncthreads();   // kv0 visible to ALL threads (nt >= 2 always here)

    float o[8][4];
#pragma unroll
    for (int j = 0; j < 8; j++)
#pragma unroll
        for (int e = 0; e < 4; e++) o[j][e] = 0.f;
    float m0r = -1e30f, m1r = -1e30f, l0 = 0.f, l1 = 0.f;

    int r0g = q0 + wid*16 + (lane >> 2);
    int cl2 = 2*(lane & 3);

    for (int t = 0; t < nt; t++) {
        int buf = t & 1;
        uint32_t kb = sb + buf * BUF_SZ;

        // warps 0-3 are entirely masked on the last kv tile (cols >= q0+64 > rows)
        bool active = !(t == 2*qb + 1 && wid < 4);
        if (active) {

        // S = Q K^T (fp16x3)
        float s[8][4];
#pragma unroll
        for (int j = 0; j < 8; j++)
#pragma unroll
            for (int e = 0; e < 4; e++) s[j][e] = 0.f;
#pragma unroll
        for (int p = 0; p < 4; p++) {
#pragma unroll
            for (int kd = 0; kd < 4; kd++) {
                uint32_t bh4[4], bl4[4];
                uint32_t ro = (uint32_t)(p*16 + lr) * KSTR + (kd*16 + lc) * 2;
                ldsm_x4(bh4, kb + ro);
                ldsm_x4(bl4, kb + A_KL + ro);
                mma16816(s[2*p],   aqh[kd], bh4[0], bh4[2]);
                mma16816(s[2*p+1], aqh[kd], bh4[1], bh4[3]);
                mma16816(s[2*p],   aql[kd], bh4[0], bh4[2]);
                mma16816(s[2*p+1], aql[kd], bh4[1], bh4[3]);
                mma16816(s[2*p],   aqh[kd], bl4[0], bl4[2]);
                mma16816(s[2*p+1], aqh[kd], bl4[1], bl4[3]);
            }
        }

        // causal mask (only last two kv tiles cross the diagonal)
        if (t >= 2*qb) {
            int r1g = r0g + 8;
#pragma unroll
            for (int j = 0; j < 8; j++) {
                int c0 = 64*t + 8*j + cl2;
                if (c0     > r0g) s[j][0] = -1e30f;
                if (c0 + 1 > r0g) s[j][1] = -1e30f;
                if (c0     > r1g) s[j][2] = -1e30f;
                if (c0 + 1 > r1g) s[j][3] = -1e30f;
            }
        }

        // online softmax (log2 domain; Q pre-scaled by log2e/8)
        float rm0 = -1e30f, rm1 = -1e30f;
#pragma unroll
        for (int j = 0; j < 8; j++) {
            rm0 = fmaxf(rm0, fmaxf(s[j][0], s[j][1]));
            rm1 = fmaxf(rm1, fmaxf(s[j][2], s[j][3]));
        }
        rm0 = fmaxf(rm0, __shfl_xor_sync(0xffffffffu, rm0, 1));
        rm0 = fmaxf(rm0, __shfl_xor_sync(0xffffffffu, rm0, 2));
        rm1 = fmaxf(rm1, __shfl_xor_sync(0xffffffffu, rm1, 1));
        rm1 = fmaxf(rm1, __shfl_xor_sync(0xffffffffu, rm1, 2));
        float mn0 = fmaxf(m0r, rm0), mn1 = fmaxf(m1r, rm1);
        float a0 = ex2(m0r - mn0), a1 = ex2(m1r - mn1);
        float sum0 = 0.f, sum1 = 0.f;
#pragma unroll
        for (int j = 0; j < 8; j++) {
            s[j][0] = ex2(s[j][0] - mn0);
            s[j][1] = ex2(s[j][1] - mn0);
            s[j][2] = ex2(s[j][2] - mn1);
            s[j][3] = ex2(s[j][3] - mn1);
            sum0 += s[j][0] + s[j][1];
            sum1 += s[j][2] + s[j][3];
        }
        sum0 += __shfl_xor_sync(0xffffffffu, sum0, 1);
        sum0 += __shfl_xor_sync(0xffffffffu, sum0, 2);
        sum1 += __shfl_xor_sync(0xffffffffu, sum1, 1);
        sum1 += __shfl_xor_sync(0xffffffffu, sum1, 2);
        l0 = l0 * a0 + sum0;  l1 = l1 * a1 + sum1;
        m0r = mn0;  m1r = mn1;
#pragma unroll
        for (int j = 0; j < 8; j++) {
            o[j][0] *= a0; o[j][1] *= a0; o[j][2] *= a1; o[j][3] *= a1;
        }

        // O += P @ V (single product: P rn fp16, V single)
#pragma unroll
        for (int kk = 0; kk < 4; kk++) {
            uint32_t ph[4];
            ph[0] = f16x2(s[2*kk][0],   s[2*kk][1]);
            ph[1] = f16x2(s[2*kk][2],   s[2*kk][3]);
            ph[2] = f16x2(s[2*kk+1][0], s[2*kk+1][1]);
            ph[3] = f16x2(s[2*kk+1][2], s[2*kk+1][3]);
#pragma unroll
            for (int pd = 0; pd < 4; pd++) {
                uint32_t vh4[4];
                uint32_t ro = (uint32_t)(pd*16 + lr) * VSTR + (kk*16 + lc) * 2;
                ldsm_x4(vh4, kb + A_VH + ro);
                mma16816(o[2*pd],   ph, vh4[0], vh4[2]);
                mma16816(o[2*pd+1], ph, vh4[1], vh4[3]);
            }
        }

        } // active

        // pipeline: ensure t+1 visible, recycle buf for t+2
        if (t + 1 < nt) {
            asm volatile("cp.async.wait_group 0;" ::: "memory");
            __syncthreads();   // all done reading buf; t+1 visible to all
            if (t + 2 < nt)
                attn_load_kv(sb, buf, t + 2, tid, Kh, Kl, Vth);
        }
    }

    // epilogue: normalize, single rn fp16, write [B,S,D]
    float i0 = 1.f / l0, i1 = 1.f / l1;
    int b = bh >> 4, h = bh & 15;
    int s0 = q0 + wid*16 + (lane >> 2);
#pragma unroll
    for (int j = 0; j < 8; j++) {
        int d = h*64 + 8*j + cl2;
        size_t a0 = ((size_t)b*SEQ + s0) * D_MODEL + d;
        size_t a1 = a0 + (size_t)8 * D_MODEL;
        *(uint32_t*)(g_ah + a0) = f16x2(o[j][0]*i0, o[j][1]*i0);
        *(uint32_t*)(g_ah + a1) = f16x2(o[j][2]*i1, o[j][3]*i1);
    }
}

extern "C" void kernel_launch(void* const* d_in, const int* in_sizes, int n_in,
                              void* d_out, int out_size)
{
    const float* x  = (const float*)d_in[0];
    const float* wq = (const float*)d_in[1];
    const float* wk = (const float*)d_in[2];
    const float* wv = (const float*)d_in[3];
    const float* wo = (const float*)d_in[4];
    float* out = (float*)d_out;

    cudaFuncSetAttribute(mma_gemm_kernel,
                         cudaFuncAttributeMaxDynamicSharedMemorySize, GEMM_SMEM);
    cudaFuncSetAttribute(attn_mma_kernel,
                         cudaFuncAttributeMaxDynamicSharedMemorySize, ATTN_SMEM);

    const int NX = MTOT * D_MODEL;

    dim3 gs(NX/8/256, 5);
    allsplit_kernel<<<gs, 256>>>(x, wq, wk, wv, wo);

    // QKV projection (Q,K hi/lo 3-prod BK32; V 1-prod BK64 -> fp16 V^T)
    dim3 g1(MTOT/128, 24);
    mma_gemm_kernel<<<g1, 256, GEMM_SMEM>>>(nullptr, 0);

    // tensor-core causal flash attention (single-fp16 output)
    dim3 g2(SEQ/128, BATCH*NH);
    attn_mma_kernel<<<g2, 256, ATTN_SMEM>>>();

    // O-projection (1-prod BK64)
    dim3 g3(MTOT/128, D_MODEL/128);
    mma_gemm_kernel<<<g3, 256, GEMM_SMEM>>>(out, 1);
}